// round 16
// baseline (speedup 1.0000x reference)
#include <cuda_runtime.h>
#include <cuda_fp16.h>
#include <math.h>
#include <stdint.h>

#define N_NODES 20000
#define MPAD    20096            // 157 * 128
#define N_EDGES 320000
#define NREL 9
#define NB 9
#define IN_DIM 128
#define HID_DIM 256
#define OUT_DIM 64
#define W1_COLS ((NREL + 1) * HID_DIM)   // 2560
#define W2_COLS ((NREL + 1) * OUT_DIM)   // 640
#define LN_EPS 1e-5f
#define SCAN_BLOCKS 80                   // 80 * 256 = 20480 >= N_NODES
#define MCHUNK0 79                       // pipeline chunk 0: 79*128 = 10112 rows
#define MCHUNK1 78                       // pipeline chunk 1: 78*128 = 9984 rows

// ---------------- static device scratch ----------------
__device__ __half g_xh[(size_t)MPAD * IN_DIM];            // x in fp16, padded
__device__ __half g_W1t[W1_COLS * IN_DIM];                // [2560,128] K-major fp16
__device__ __half g_W2t[W2_COLS * HID_DIM];               // [640,256]  K-major fp16
__device__ __half g_Y1[(size_t)MPAD * W1_COLS];           // ~103 MB
__device__ __half g_Y2[(size_t)MPAD * W2_COLS];           // ~26 MB
__device__ __half g_h[(size_t)MPAD * HID_DIM];            // ~10 MB fp16
__device__ float  g_accA[(size_t)N_NODES * (HID_DIM / 2)];// 10 MB: v for features 0..127
__device__ int    g_counts[N_NODES];
__device__ int    g_offsets[N_NODES];
__device__ int    g_cursor[N_NODES];
__device__ int    g_rowid[N_EDGES];
__device__ int    g_blocksum[SCAN_BLOCKS];

// ---------------- helpers ----------------
static __device__ __forceinline__ uint32_t smem_u32(const void* p) {
    uint32_t a;
    asm("{ .reg .u64 t; cvta.to.shared.u64 t, %1; cvt.u32.u64 %0, t; }" : "=r"(a) : "l"(p));
    return a;
}

#if defined(__CUDA_ARCH__) && defined(__CUDA_ARCH_FEAT_SM103_ALL)
#define HAS_TCGEN05 1
#else
#define HAS_TCGEN05 0
#endif

#if HAS_TCGEN05
static __device__ __forceinline__ uint32_t elect_one() {
    uint32_t p;
    asm volatile("{\n\t.reg .pred p;\n\telect.sync _|p, 0xFFFFFFFF;\n\tselp.b32 %0, 1, 0, p;\n\t}" : "=r"(p));
    return p;
}
static __device__ __forceinline__ void mbar_init(uint32_t a, uint32_t cnt) {
    asm volatile("mbarrier.init.shared.b64 [%0], %1;" :: "r"(a), "r"(cnt) : "memory");
}
static __device__ __forceinline__ void mbar_wait(uint32_t a, uint32_t parity) {
    asm volatile(
        "{\n\t.reg .pred P;\n\t"
        "WL_%=:\n\t"
        "mbarrier.try_wait.parity.acquire.cta.shared::cta.b64 P, [%0], %1, 0x989680;\n\t"
        "@P bra WD_%=;\n\t"
        "bra WL_%=;\n\t"
        "WD_%=:\n\t}"
        :: "r"(a), "r"(parity) : "memory");
}
static __device__ __forceinline__ void tmem_alloc(uint32_t dst_smem, uint32_t ncols) {
    asm volatile("tcgen05.alloc.cta_group::1.sync.aligned.shared::cta.b32 [%0], %1;"
                 :: "r"(dst_smem), "r"(ncols) : "memory");
}
static __device__ __forceinline__ void tmem_dealloc(uint32_t tmem, uint32_t ncols) {
    asm volatile("tcgen05.dealloc.cta_group::1.sync.aligned.b32 %0, %1;" :: "r"(tmem), "r"(ncols));
}
static __device__ __forceinline__ void tmem_relinquish() {
    asm volatile("tcgen05.relinquish_alloc_permit.cta_group::1.sync.aligned;");
}
static __device__ __forceinline__ void tc_commit(uint32_t mbar) {
    asm volatile("tcgen05.commit.cta_group::1.mbarrier::arrive::one.shared::cluster.b64 [%0];"
                 :: "r"(mbar) : "memory");
}
static __device__ __forceinline__ void mma_f16_ss(uint32_t d, uint64_t adesc, uint64_t bdesc,
                                                  uint32_t idesc, uint32_t en) {
    asm volatile(
        "{\n\t.reg .pred p;\n\t"
        "setp.ne.u32 p, %5, 0;\n\t"
        "tcgen05.mma.cta_group::1.kind::f16 [%0], %1, %2, %3, {%4, %4, %4, %4}, p;\n\t}"
        :: "r"(d), "l"(adesc), "l"(bdesc), "r"(idesc), "r"(0u), "r"(en)
        : "memory");
}
// SW128 K-major SMEM descriptor: layout=SW128(2), version=1, SBO=64, LBO=1
static __device__ __forceinline__ uint64_t make_desc(uint32_t smem_addr) {
    const uint64_t base = (uint64_t(2) << 61) | (uint64_t(1) << 46) | (uint64_t(64) << 32) | (uint64_t(1) << 16);
    return base | ((uint64_t)(smem_addr >> 4) & 0x3FFF);
}
// swizzled store of 8 fp16 (16B) at (row r, fp16-col c, c % 8 == 0) of a 128x128 fp16 tile
static __device__ __forceinline__ void sts_h8(char* tile, int r, int c, uint4 v) {
    int off = ((r >> 3) + (c >> 6) * 16) * 1024 + (r & 7) * 128 + (c & 63) * 2;
    off ^= (off >> 3) & 0x70;
    *(uint4*)(tile + off) = v;
}
static __device__ __forceinline__ uint32_t pack_h2(uint32_t a, uint32_t b) {
    __half2 h = __floats2half2_rn(__uint_as_float(a), __uint_as_float(b));
    return *(uint32_t*)&h;
}

#define LDTM_X32(r, addr) \
    asm volatile( \
        "tcgen05.ld.sync.aligned.32x32b.x32.b32 " \
        "{%0, %1, %2, %3, %4, %5, %6, %7, " \
        " %8, %9, %10, %11, %12, %13, %14, %15, " \
        " %16, %17, %18, %19, %20, %21, %22, %23, " \
        " %24, %25, %26, %27, %28, %29, %30, %31}, [%32];" \
        : "=r"((r)[0]),  "=r"((r)[1]),  "=r"((r)[2]),  "=r"((r)[3]), \
          "=r"((r)[4]),  "=r"((r)[5]),  "=r"((r)[6]),  "=r"((r)[7]), \
          "=r"((r)[8]),  "=r"((r)[9]),  "=r"((r)[10]), "=r"((r)[11]), \
          "=r"((r)[12]), "=r"((r)[13]), "=r"((r)[14]), "=r"((r)[15]), \
          "=r"((r)[16]), "=r"((r)[17]), "=r"((r)[18]), "=r"((r)[19]), \
          "=r"((r)[20]), "=r"((r)[21]), "=r"((r)[22]), "=r"((r)[23]), \
          "=r"((r)[24]), "=r"((r)[25]), "=r"((r)[26]), "=r"((r)[27]), \
          "=r"((r)[28]), "=r"((r)[29]), "=r"((r)[30]), "=r"((r)[31]) \
        : "r"(addr))
#endif  // HAS_TCGEN05

// ---------------- fused prep: x -> fp16 (padded) + build W1^T ----------------
#define X2H_BLOCKS ((MPAD * IN_DIM / 4 + 255) / 256)
#define BW1_BLOCKS ((W1_COLS * IN_DIM + 255) / 256)
__global__ void k_prep1(const float* __restrict__ x, const float* __restrict__ bases,
                        const float* __restrict__ comp, const float* __restrict__ root) {
    if (blockIdx.x < X2H_BLOCKS) {
        int idx = blockIdx.x * 256 + threadIdx.x;
        if (idx >= MPAD * IN_DIM / 4) return;
        int row = idx / (IN_DIM / 4);
        __half2 h0 = __half2(__float2half(0.f), __float2half(0.f)), h1 = h0;
        if (row < N_NODES) {
            float4 v = *(const float4*)(x + (size_t)idx * 4);
            h0 = __floats2half2_rn(v.x, v.y);
            h1 = __floats2half2_rn(v.z, v.w);
        }
        __half2* o = (__half2*)g_xh + (size_t)idx * 2;
        o[0] = h0; o[1] = h1;
    } else {
        int idx = (blockIdx.x - X2H_BLOCKS) * 256 + threadIdx.x;
        if (idx >= W1_COLS * IN_DIM) return;
        int col = idx / IN_DIM, k = idx % IN_DIM;
        int r = col / HID_DIM, o = col % HID_DIM;
        float v;
        if (r == NREL) v = root[k * HID_DIM + o];
        else {
            v = 0.f;
#pragma unroll
            for (int b = 0; b < NB; b++)
                v += comp[r * NB + b] * bases[((size_t)b * IN_DIM + k) * HID_DIM + o];
        }
        g_W1t[idx] = __float2half(v);
    }
}

// ---------------- CSR build ----------------
__global__ void k_zero_counts() {
    int i = blockIdx.x * blockDim.x + threadIdx.x;
    if (i < N_NODES) g_counts[i] = 0;
}
__global__ void k_count(const int* __restrict__ ei) {
    int e = blockIdx.x * blockDim.x + threadIdx.x;
    if (e < N_EDGES) atomicAdd(&g_counts[ei[N_EDGES + e]], 1);
}
__global__ void __launch_bounds__(256) k_scan1() {
    int t = threadIdx.x, lane = t & 31, w = t >> 5;
    int i = blockIdx.x * 256 + t;
    int v = (i < N_NODES) ? g_counts[i] : 0;
    int x = v;
#pragma unroll
    for (int o = 1; o < 32; o <<= 1) {
        int y = __shfl_up_sync(0xffffffffu, x, o);
        if (lane >= o) x += y;
    }
    __shared__ int ws[8];
    if (lane == 31) ws[w] = x;
    __syncthreads();
    int add = 0;
#pragma unroll
    for (int k = 0; k < 8; k++) add += (k < w) ? ws[k] : 0;
    if (i < N_NODES) g_offsets[i] = x - v + add;
    if (t == 255) g_blocksum[blockIdx.x] = x + add;
}
__global__ void __launch_bounds__(128) k_scan2() {
    int t = threadIdx.x, lane = t & 31, w = t >> 5;
    int v = (t < SCAN_BLOCKS) ? g_blocksum[t] : 0;
    int x = v;
#pragma unroll
    for (int o = 1; o < 32; o <<= 1) {
        int y = __shfl_up_sync(0xffffffffu, x, o);
        if (lane >= o) x += y;
    }
    __shared__ int ws[4];
    if (lane == 31) ws[w] = x;
    __syncthreads();
    int add = 0;
#pragma unroll
    for (int k = 0; k < 4; k++) add += (k < w) ? ws[k] : 0;
    if (t < SCAN_BLOCKS) g_blocksum[t] = x - v + add;
}
__global__ void __launch_bounds__(256) k_scan3() {
    int i = blockIdx.x * 256 + threadIdx.x;
    if (i < N_NODES) {
        int o = g_offsets[i] + g_blocksum[blockIdx.x];
        g_offsets[i] = o;
        g_cursor[i]  = o;
    }
}
__global__ void k_scatter(const int* __restrict__ ei, const int* __restrict__ et) {
    int e = blockIdx.x * blockDim.x + threadIdx.x;
    if (e < N_EDGES) {
        int dst = ei[N_EDGES + e];
        int pos = atomicAdd(&g_cursor[dst], 1);
        g_rowid[pos] = ei[e] * (NREL + 1) + et[e];
    }
}

// ---------------- build W2^T (K-major, fp16) ----------------
__global__ void k_buildW2t(const float* __restrict__ bases, const float* __restrict__ comp,
                           const float* __restrict__ root) {
    int idx = blockIdx.x * blockDim.x + threadIdx.x;
    if (idx >= W2_COLS * HID_DIM) return;
    int col = idx / HID_DIM, k = idx % HID_DIM;
    int r = col / OUT_DIM, o = col % OUT_DIM;
    float v;
    if (r == NREL) v = root[k * OUT_DIM + o];
    else {
        v = 0.f;
#pragma unroll
        for (int b = 0; b < NB; b++)
            v += comp[r * NB + b] * bases[((size_t)b * HID_DIM + k) * OUT_DIM + o];
    }
    g_W2t[idx] = __float2half(v);
}

// ---------------- GEMM: C[rows,N](fp16) = A[rows,K](fp16) @ Bt[N,K]^T(fp16) ----------------
// 256 threads, CTA tile 128x128; colBase = (bx*colMul + colAdd)*128 for column grouping.
__global__ void __launch_bounds__(256)
k_tc_gemm(const __half* __restrict__ A, const __half* __restrict__ Bt,
          __half* __restrict__ C, int Ktot, int N, int row0, int colMul, int colAdd) {
#if HAS_TCGEN05
    extern __shared__ char smem[];
    const uint32_t sb = smem_u32(smem);
    char* sA = smem + 1024;
    char* sB = smem + 1024 + 32768;
    int tid = threadIdx.x, wid = tid >> 5, lid = tid & 31;
    int rowBase = (blockIdx.y + row0) * 128;
    int colBase = (blockIdx.x * colMul + colAdd) * 128;

    if (wid == 0) { tmem_alloc(sb, 128); tmem_relinquish(); }
    if (tid == 0) mbar_init(sb + 8, 1);
    __syncthreads();
    uint32_t tmem;
    asm volatile("ld.shared.b32 %0, [%1];" : "=r"(tmem) : "r"(sb));

    const uint32_t idesc = 0x8200010u;
    const uint64_t da = make_desc(sb + 1024);
    const uint64_t db = make_desc(sb + 1024 + 32768);

    int nKc = Ktot >> 7;
    for (int kc = 0; kc < nKc; kc++) {
        if (kc > 0) mbar_wait(sb + 8, (kc - 1) & 1);
        int k0 = kc << 7;
#pragma unroll
        for (int i = 0; i < 8; i++) {
            int fid = i * 256 + tid;
            int r = fid >> 4;
            int c = (fid & 15) * 8;
            uint4 va = *(const uint4*)(A + (size_t)(rowBase + r) * Ktot + k0 + c);
            sts_h8(sA, r, c, va);
            uint4 vb = *(const uint4*)(Bt + (size_t)(colBase + r) * Ktot + k0 + c);
            sts_h8(sB, r, c, vb);
        }
        asm volatile("fence.proxy.async.shared::cta;" ::: "memory");
        __syncthreads();
        if (wid == 0) {
            if (elect_one()) {
#pragma unroll
                for (int ks = 0; ks < 8; ks++) {
                    uint64_t off = (uint64_t)((ks >> 2) * 1024 + (ks & 3) * 2);
                    mma_f16_ss(tmem, da + off, db + off, idesc, (kc | ks) != 0);
                }
                tc_commit(sb + 8);
            }
        }
    }
    mbar_wait(sb + 8, (nKc - 1) & 1);
    asm volatile("tcgen05.fence::after_thread_sync;" ::: "memory");

    uint32_t* hstg = (uint32_t*)(smem + 1024) + wid * (32 * 33);
    int rowOff = (wid & 3) * 32;
    int colOff = (wid >> 2) * 64;
    uint32_t rg0[32], rg1[32];
    LDTM_X32(rg0, tmem + colOff);
    LDTM_X32(rg1, tmem + colOff + 32);
    asm volatile("tcgen05.wait::ld.sync.aligned;" ::: "memory");
#pragma unroll
    for (int j = 0; j < 16; j++) {
        hstg[lid * 33 + j]      = pack_h2(rg0[2 * j], rg0[2 * j + 1]);
        hstg[lid * 33 + 16 + j] = pack_h2(rg1[2 * j], rg1[2 * j + 1]);
    }
    __syncwarp();
    uint32_t* crow = (uint32_t*)(C + (size_t)(rowBase + rowOff) * N + colBase + colOff);
#pragma unroll 4
    for (int rr = 0; rr < 32; rr++)
        crow[(size_t)rr * (N / 2) + lid] = hstg[rr * 33 + lid];

    asm volatile("tcgen05.fence::before_thread_sync;" ::: "memory");
    __syncthreads();
    if (wid == 0) tmem_dealloc(tmem, 128);
#else
    // ---- SIMT fallback (non-sm_103a passes), correctness only ----
    extern __shared__ char smem[];
    float* As = (float*)smem;
    float* Bs = (float*)smem + 8 * 128;
    int tid = threadIdx.x;
    int rowBase = (blockIdx.y + row0) * 128;
    int colBase = (blockIdx.x * colMul + colAdd) * 128;
    int tr = (tid >> 4) * 8;
    int tc = (tid & 15) * 8;

    float acc[8][8] = {};
    for (int k0 = 0; k0 < Ktot; k0 += 8) {
        if (tid < 128) {
            uint4 av = *(const uint4*)(A + (size_t)(rowBase + tid) * Ktot + k0);
            const __half2* ah = (const __half2*)&av;
#pragma unroll
            for (int j = 0; j < 4; j++) {
                float2 f = __half22float2(ah[j]);
                As[(2 * j) * 128 + tid] = f.x;
                As[(2 * j + 1) * 128 + tid] = f.y;
            }
        } else {
            int t2 = tid - 128;
            uint4 bv = *(const uint4*)(Bt + (size_t)(colBase + t2) * Ktot + k0);
            const __half2* bh = (const __half2*)&bv;
#pragma unroll
            for (int j = 0; j < 4; j++) {
                float2 f = __half22float2(bh[j]);
                Bs[(2 * j) * 128 + t2] = f.x;
                Bs[(2 * j + 1) * 128 + t2] = f.y;
            }
        }
        __syncthreads();
#pragma unroll
        for (int kk = 0; kk < 8; kk++) {
            float rm[8], rn[8];
#pragma unroll
            for (int i = 0; i < 8; i++) rm[i] = As[kk * 128 + tr + i];
#pragma unroll
            for (int j = 0; j < 8; j++) rn[j] = Bs[kk * 128 + tc + j];
#pragma unroll
            for (int i = 0; i < 8; i++)
#pragma unroll
                for (int j = 0; j < 8; j++) acc[i][j] += rm[i] * rn[j];
        }
        __syncthreads();
    }
#pragma unroll
    for (int i = 0; i < 8; i++) {
        int row = rowBase + tr + i;
#pragma unroll
        for (int j = 0; j < 8; j++)
            C[(size_t)row * N + colBase + tc + j] = __float2half(acc[i][j]);
    }
#endif
}

// ---------------- layer 1 phase A: gather-max over features 0..127 -> g_accA ----------------
// 64 threads per node; each thread owns 2 features via half2.
__global__ void __launch_bounds__(64) k_agg1A(const float* __restrict__ bias) {
    int n = blockIdx.x;
    int t = threadIdx.x;                 // 0..63 -> features 2t, 2t+1
    int start = g_offsets[n];
    int deg = g_counts[n];
    const __half2* Y = (const __half2*)g_Y1;

    float mx = -INFINITY, my = -INFINITY;
    int i = 0;
    for (; i + 8 <= deg; i += 8) {
        int r_[8];
#pragma unroll
        for (int u = 0; u < 8; u++) r_[u] = g_rowid[start + i + u];
        float2 f_[8];
#pragma unroll
        for (int u = 0; u < 8; u++) f_[u] = __half22float2(Y[(size_t)r_[u] * (HID_DIM / 2) + t]);
#pragma unroll
        for (int u = 0; u < 8; u++) { mx = fmaxf(mx, f_[u].x); my = fmaxf(my, f_[u].y); }
    }
    for (; i < deg; i++) {
        int row = g_rowid[start + i];
        float2 f = __half22float2(Y[(size_t)row * (HID_DIM / 2) + t]);
        mx = fmaxf(mx, f.x);
        my = fmaxf(my, f.y);
    }
    if (deg == 0) { mx = 0.f; my = 0.f; }

    float2 rootv = __half22float2(Y[((size_t)n * W1_COLS + NREL * HID_DIM) / 2 + t]);
    float2 bi = ((const float2*)bias)[t];
    ((float2*)g_accA)[(size_t)n * 64 + t] = make_float2(mx + rootv.x + bi.x, my + rootv.y + bi.y);
}

// ---------------- layer 1 phase B: gather-max features 128..255 + combine + LN + ReLU ----------------
// 64 threads per node; each thread owns A-features (2t,2t+1) from g_accA and B-features (128+2t,129+2t).
__global__ void __launch_bounds__(64) k_agg1B(const float* __restrict__ bias,
                                              const float* __restrict__ gamma,
                                              const float* __restrict__ beta,
                                              int n0) {
    int n = blockIdx.x + n0;
    int t = threadIdx.x;                 // 0..63
    __half2* H = (__half2*)g_h;
    if (n >= N_NODES) {                  // zero pad rows for GEMM2
        __half2 z = __half2(__half(0.f), __half(0.f));
        H[(size_t)n * (HID_DIM / 2) + t] = z;
        H[(size_t)n * (HID_DIM / 2) + 64 + t] = z;
        return;
    }
    int start = g_offsets[n];
    int deg = g_counts[n];
    const __half2* Y = (const __half2*)g_Y1;

    float mx = -INFINITY, my = -INFINITY;
    int i = 0;
    for (; i + 8 <= deg; i += 8) {
        int r_[8];
#pragma unroll
        for (int u = 0; u < 8; u++) r_[u] = g_rowid[start + i + u];
        float2 f_[8];
#pragma unroll
        for (int u = 0; u < 8; u++) f_[u] = __half22float2(Y[(size_t)r_[u] * (HID_DIM / 2) + 64 + t]);
#pragma unroll
        for (int u = 0; u < 8; u++) { mx = fmaxf(mx, f_[u].x); my = fmaxf(my, f_[u].y); }
    }
    for (; i < deg; i++) {
        int row = g_rowid[start + i];
        float2 f = __half22float2(Y[(size_t)row * (HID_DIM / 2) + 64 + t]);
        mx = fmaxf(mx, f.x);
        my = fmaxf(my, f.y);
    }
    if (deg == 0) { mx = 0.f; my = 0.f; }

    float2 rootv = __half22float2(Y[((size_t)n * W1_COLS + NREL * HID_DIM) / 2 + 64 + t]);
    float2 biB = ((const float2*)bias)[64 + t];
    float bx = mx + rootv.x + biB.x;
    float by = my + rootv.y + biB.y;

    float2 av = ((const float2*)g_accA)[(size_t)n * 64 + t];

    // LayerNorm over 256 (4 values per thread, 64 threads = 2 warps)
    float s  = av.x + av.y + bx + by;
    float s2 = av.x * av.x + av.y * av.y + bx * bx + by * by;
#pragma unroll
    for (int o = 16; o > 0; o >>= 1) {
        s  += __shfl_xor_sync(0xffffffffu, s, o);
        s2 += __shfl_xor_sync(0xffffffffu, s2, o);
    }
    __shared__ float ws[2], ws2[2];
    int w = t >> 5, l = t & 31;
    if (l == 0) { ws[w] = s; ws2[w] = s2; }
    __syncthreads();
    float ts = ws[0] + ws[1], ts2 = ws2[0] + ws2[1];
    float mean = ts * (1.f / HID_DIM);
    float var  = ts2 * (1.f / HID_DIM) - mean * mean;
    float rstd = rsqrtf(var + LN_EPS);
    float2 gaA = ((const float2*)gamma)[t];
    float2 beA = ((const float2*)beta)[t];
    float2 gaB = ((const float2*)gamma)[64 + t];
    float2 beB = ((const float2*)beta)[64 + t];
    float yax = (av.x - mean) * rstd * gaA.x + beA.x;
    float yay = (av.y - mean) * rstd * gaA.y + beA.y;
    float ybx = (bx - mean) * rstd * gaB.x + beB.x;
    float yby = (by - mean) * rstd * gaB.y + beB.y;
    H[(size_t)n * (HID_DIM / 2) + t]      = __floats2half2_rn(fmaxf(yax, 0.f), fmaxf(yay, 0.f));
    H[(size_t)n * (HID_DIM / 2) + 64 + t] = __floats2half2_rn(fmaxf(ybx, 0.f), fmaxf(yby, 0.f));
}

// ---------------- layer 2: gather-sum + root + bias + LN + log_softmax ----------------
__global__ void __launch_bounds__(256) k_agg2(const float* __restrict__ bias,
                                              const float* __restrict__ gamma,
                                              const float* __restrict__ beta,
                                              float* __restrict__ out) {
    int n = blockIdx.x * 8 + (threadIdx.x >> 5);
    if (n >= N_NODES) return;
    int lane = threadIdx.x & 31;
    int start = g_offsets[n];
    int deg = g_counts[n];
    const __half2* Y = (const __half2*)g_Y2;

    float sx = 0.f, sy = 0.f;
    int i = 0;
    for (; i + 8 <= deg; i += 8) {
        int r_[8];
#pragma unroll
        for (int u = 0; u < 8; u++) r_[u] = g_rowid[start + i + u];
        float2 f_[8];
#pragma unroll
        for (int u = 0; u < 8; u++) f_[u] = __half22float2(Y[(size_t)r_[u] * (OUT_DIM / 2) + lane]);
#pragma unroll
        for (int u = 0; u < 8; u++) { sx += f_[u].x; sy += f_[u].y; }
    }
    for (; i < deg; i++) {
        int row = g_rowid[start + i];
        float2 f = __half22float2(Y[(size_t)row * (OUT_DIM / 2) + lane]);
        sx += f.x; sy += f.y;
    }
    float2 rootv = __half22float2(Y[((size_t)n * W2_COLS + NREL * OUT_DIM) / 2 + lane]);
    float2 bi = ((const float2*)bias)[lane];
    float vx = sx + rootv.x + bi.x;
    float vy = sy + rootv.y + bi.y;

    float a = vx + vy, b = vx * vx + vy * vy;
#pragma unroll
    for (int o = 16; o > 0; o >>= 1) {
        a += __shfl_xor_sync(0xffffffffu, a, o);
        b += __shfl_xor_sync(0xffffffffu, b, o);
    }
    float mean = a * (1.f / OUT_DIM);
    float var  = b * (1.f / OUT_DIM) - mean * mean;
    float rstd = rsqrtf(var + LN_EPS);
    float2 ga = ((const float2*)gamma)[lane];
    float2 be = ((const float2*)beta)[lane];
    float yx = (vx - mean) * rstd * ga.x + be.x;
    float yy = (vy - mean) * rstd * ga.y + be.y;

    float mx = fmaxf(yx, yy);
#pragma unroll
    for (int o = 16; o > 0; o >>= 1) mx = fmaxf(mx, __shfl_xor_sync(0xffffffffu, mx, o));
    float es = expf(yx - mx) + expf(yy - mx);
#pragma unroll
    for (int o = 16; o > 0; o >>= 1) es += __shfl_xor_sync(0xffffffffu, es, o);
    float lse = mx + logf(es);

    ((float2*)out)[(size_t)n * (OUT_DIM / 2) + lane] = make_float2(yx - lse, yy - lse);
}

// ---------------- host launch ----------------
extern "C" void kernel_launch(void* const* d_in, const int* in_sizes, int n_in,
                              void* d_out, int out_size) {
    const float* x      = (const float*)d_in[0];
    const int*   ei     = (const int*)d_in[1];
    const int*   et     = (const int*)d_in[2];
    const float* bases1 = (const float*)d_in[3];
    const float* comp1  = (const float*)d_in[4];
    const float* root1  = (const float*)d_in[5];
    const float* bias1  = (const float*)d_in[6];
    const float* g1     = (const float*)d_in[7];
    const float* b1     = (const float*)d_in[8];
    const float* bases2 = (const float*)d_in[9];
    const float* comp2  = (const float*)d_in[10];
    const float* root2  = (const float*)d_in[11];
    const float* bias2  = (const float*)d_in[12];
    const float* g2     = (const float*)d_in[13];
    const float* b2     = (const float*)d_in[14];
    float* out = (float*)d_out;

    __half *pxh, *pW1t, *pW2t, *pY1, *pY2, *ph;
    cudaGetSymbolAddress((void**)&pxh,  g_xh);
    cudaGetSymbolAddress((void**)&pW1t, g_W1t);
    cudaGetSymbolAddress((void**)&pW2t, g_W2t);
    cudaGetSymbolAddress((void**)&pY1,  g_Y1);
    cudaGetSymbolAddress((void**)&pY2,  g_Y2);
    cudaGetSymbolAddress((void**)&ph,   g_h);

    const int SMEM_GEMM = 1024 + 2 * 32768;   // 66560 B
    cudaFuncSetAttribute(k_tc_gemm, cudaFuncAttributeMaxDynamicSharedMemorySize, SMEM_GEMM);

    // lazy one-time stream/event creation (identical work every call)
    static cudaStream_t s2 = nullptr;
    static cudaEvent_t evFork = nullptr, evGA = nullptr, evA1A = nullptr, evB0 = nullptr, evG2a = nullptr;
    if (s2 == nullptr) {
        cudaStreamCreateWithFlags(&s2, cudaStreamNonBlocking);
        cudaEventCreateWithFlags(&evFork, cudaEventDisableTiming);
        cudaEventCreateWithFlags(&evGA, cudaEventDisableTiming);
        cudaEventCreateWithFlags(&evA1A, cudaEventDisableTiming);
        cudaEventCreateWithFlags(&evB0, cudaEventDisableTiming);
        cudaEventCreateWithFlags(&evG2a, cudaEventDisableTiming);
    }

    // fork: CSR chain on s2
    cudaEventRecord(evFork, 0);
    cudaStreamWaitEvent(s2, evFork, 0);

    // --- side stream: CSR build + W2 ---
    k_zero_counts<<<(N_NODES + 255) / 256, 256, 0, s2>>>();
    k_count<<<(N_EDGES + 255) / 256, 256, 0, s2>>>(ei);
    k_scan1<<<SCAN_BLOCKS, 256, 0, s2>>>();
    k_scan2<<<1, 128, 0, s2>>>();
    k_scan3<<<SCAN_BLOCKS, 256, 0, s2>>>();
    k_scatter<<<(N_EDGES + 255) / 256, 256, 0, s2>>>(ei, et);
    k_buildW2t<<<(W2_COLS * HID_DIM + 255) / 256, 256, 0, s2>>>(bases2, comp2, root2);

    // --- main stream: fused prep, GEMM1 group A (even column tiles: features 0..127) ---
    k_prep1<<<X2H_BLOCKS + BW1_BLOCKS, 256>>>(x, bases1, comp1, root1);
    {
        dim3 grid(W1_COLS / 256, MPAD / 128);        // 10 x 157
        k_tc_gemm<<<grid, 256, SMEM_GEMM>>>(pxh, pW1t, pY1, IN_DIM, W1_COLS, 0, 2, 0);
    }
    cudaEventRecord(evGA, 0);

    // s2: after CSR + GEMM1-A, run agg1A (hidden under GEMM1-B)
    cudaStreamWaitEvent(s2, evGA, 0);
    k_agg1A<<<N_NODES, 64, 0, s2>>>(bias1);
    cudaEventRecord(evA1A, s2);

    // main: GEMM1 group B (odd column tiles: features 128..255)
    {
        dim3 grid(W1_COLS / 256, MPAD / 128);
        k_tc_gemm<<<grid, 256, SMEM_GEMM>>>(pxh, pW1t, pY1, IN_DIM, W1_COLS, 0, 2, 1);
    }

    // main: agg1B pipeline with GEMM2 (needs accA + CSR via evA1A)
    cudaStreamWaitEvent(0, evA1A, 0);
    k_agg1B<<<MCHUNK0 * 128, 64>>>(bias1, g1, b1, 0);
    cudaEventRecord(evB0, 0);
    cudaStreamWaitEvent(s2, evB0, 0);
    {
        dim3 grid(W2_COLS / 128, MCHUNK0);
        k_tc_gemm<<<grid, 256, SMEM_GEMM, s2>>>(ph, pW2t, pY2, HID_DIM, W2_COLS, 0, 1, 0);
    }
    cudaEventRecord(evG2a, s2);

    k_agg1B<<<MCHUNK1 * 128, 64>>>(bias1, g1, b1, MCHUNK0 * 128);
    {
        dim3 grid(W2_COLS / 128, MCHUNK1);
        k_tc_gemm<<<grid, 256, SMEM_GEMM>>>(ph, pW2t, pY2, HID_DIM, W2_COLS, MCHUNK0, 1, 0);
    }

    // agg2 needs both GEMM2 halves
    cudaStreamWaitEvent(0, evG2a, 0);
    k_agg2<<<(N_NODES + 7) / 8, 256>>>(bias2, g2, b2, out);
}

// round 17
// speedup vs baseline: 1.0557x; 1.0557x over previous
#include <cuda_runtime.h>
#include <cuda_fp16.h>
#include <math.h>
#include <stdint.h>

#define N_NODES 20000
#define MPAD    20096            // 157 * 128
#define N_EDGES 320000
#define NREL 9
#define NB 9
#define IN_DIM 128
#define HID_DIM 256
#define OUT_DIM 64
#define W1_COLS ((NREL + 1) * HID_DIM)   // 2560
#define W2_COLS ((NREL + 1) * OUT_DIM)   // 640
#define LN_EPS 1e-5f
#define SCAN_BLOCKS 80                   // 80 * 256 = 20480 >= N_NODES
#define MCHUNK0 79                       // first chunk: 79*128 = 10112 rows
#define MCHUNK1 78                       // second chunk: 78*128 = 9984 rows

// ---------------- static device scratch ----------------
__device__ __half g_xh[(size_t)MPAD * IN_DIM];            // x in fp16, padded
__device__ __half g_W1t[W1_COLS * IN_DIM];                // [2560,128] K-major fp16
__device__ __half g_W2t[W2_COLS * HID_DIM];               // [640,256]  K-major fp16
__device__ __half g_Y1[(size_t)MPAD * W1_COLS];           // ~103 MB
__device__ __half g_Y2[(size_t)MPAD * W2_COLS];           // ~26 MB
__device__ __half g_h[(size_t)MPAD * HID_DIM];            // ~10 MB fp16
__device__ int    g_counts[N_NODES];
__device__ int    g_offsets[N_NODES];
__device__ int    g_cursor[N_NODES];
__device__ int    g_rowid[N_EDGES];
__device__ int    g_blocksum[SCAN_BLOCKS];

// ---------------- helpers ----------------
static __device__ __forceinline__ uint32_t smem_u32(const void* p) {
    uint32_t a;
    asm("{ .reg .u64 t; cvta.to.shared.u64 t, %1; cvt.u32.u64 %0, t; }" : "=r"(a) : "l"(p));
    return a;
}

#if defined(__CUDA_ARCH__) && defined(__CUDA_ARCH_FEAT_SM103_ALL)
#define HAS_TCGEN05 1
#else
#define HAS_TCGEN05 0
#endif

#if HAS_TCGEN05
static __device__ __forceinline__ uint32_t elect_one() {
    uint32_t p;
    asm volatile("{\n\t.reg .pred p;\n\telect.sync _|p, 0xFFFFFFFF;\n\tselp.b32 %0, 1, 0, p;\n\t}" : "=r"(p));
    return p;
}
static __device__ __forceinline__ void mbar_init(uint32_t a, uint32_t cnt) {
    asm volatile("mbarrier.init.shared.b64 [%0], %1;" :: "r"(a), "r"(cnt) : "memory");
}
static __device__ __forceinline__ void mbar_wait(uint32_t a, uint32_t parity) {
    asm volatile(
        "{\n\t.reg .pred P;\n\t"
        "WL_%=:\n\t"
        "mbarrier.try_wait.parity.acquire.cta.shared::cta.b64 P, [%0], %1, 0x989680;\n\t"
        "@P bra WD_%=;\n\t"
        "bra WL_%=;\n\t"
        "WD_%=:\n\t}"
        :: "r"(a), "r"(parity) : "memory");
}
static __device__ __forceinline__ void tmem_alloc(uint32_t dst_smem, uint32_t ncols) {
    asm volatile("tcgen05.alloc.cta_group::1.sync.aligned.shared::cta.b32 [%0], %1;"
                 :: "r"(dst_smem), "r"(ncols) : "memory");
}
static __device__ __forceinline__ void tmem_dealloc(uint32_t tmem, uint32_t ncols) {
    asm volatile("tcgen05.dealloc.cta_group::1.sync.aligned.b32 %0, %1;" :: "r"(tmem), "r"(ncols));
}
static __device__ __forceinline__ void tmem_relinquish() {
    asm volatile("tcgen05.relinquish_alloc_permit.cta_group::1.sync.aligned;");
}
static __device__ __forceinline__ void tc_commit(uint32_t mbar) {
    asm volatile("tcgen05.commit.cta_group::1.mbarrier::arrive::one.shared::cluster.b64 [%0];"
                 :: "r"(mbar) : "memory");
}
static __device__ __forceinline__ void mma_f16_ss(uint32_t d, uint64_t adesc, uint64_t bdesc,
                                                  uint32_t idesc, uint32_t en) {
    asm volatile(
        "{\n\t.reg .pred p;\n\t"
        "setp.ne.u32 p, %5, 0;\n\t"
        "tcgen05.mma.cta_group::1.kind::f16 [%0], %1, %2, %3, {%4, %4, %4, %4}, p;\n\t}"
        :: "r"(d), "l"(adesc), "l"(bdesc), "r"(idesc), "r"(0u), "r"(en)
        : "memory");
}
// SW128 K-major SMEM descriptor: layout=SW128(2), version=1, SBO=64, LBO=1
static __device__ __forceinline__ uint64_t make_desc(uint32_t smem_addr) {
    const uint64_t base = (uint64_t(2) << 61) | (uint64_t(1) << 46) | (uint64_t(64) << 32) | (uint64_t(1) << 16);
    return base | ((uint64_t)(smem_addr >> 4) & 0x3FFF);
}
// swizzled store of 8 fp16 (16B) at (row r, fp16-col c, c % 8 == 0) of a 128x128 fp16 tile
static __device__ __forceinline__ void sts_h8(char* tile, int r, int c, uint4 v) {
    int off = ((r >> 3) + (c >> 6) * 16) * 1024 + (r & 7) * 128 + (c & 63) * 2;
    off ^= (off >> 3) & 0x70;
    *(uint4*)(tile + off) = v;
}
static __device__ __forceinline__ uint32_t pack_h2(uint32_t a, uint32_t b) {
    __half2 h = __floats2half2_rn(__uint_as_float(a), __uint_as_float(b));
    return *(uint32_t*)&h;
}

#define LDTM_X32(r, addr) \
    asm volatile( \
        "tcgen05.ld.sync.aligned.32x32b.x32.b32 " \
        "{%0, %1, %2, %3, %4, %5, %6, %7, " \
        " %8, %9, %10, %11, %12, %13, %14, %15, " \
        " %16, %17, %18, %19, %20, %21, %22, %23, " \
        " %24, %25, %26, %27, %28, %29, %30, %31}, [%32];" \
        : "=r"((r)[0]),  "=r"((r)[1]),  "=r"((r)[2]),  "=r"((r)[3]), \
          "=r"((r)[4]),  "=r"((r)[5]),  "=r"((r)[6]),  "=r"((r)[7]), \
          "=r"((r)[8]),  "=r"((r)[9]),  "=r"((r)[10]), "=r"((r)[11]), \
          "=r"((r)[12]), "=r"((r)[13]), "=r"((r)[14]), "=r"((r)[15]), \
          "=r"((r)[16]), "=r"((r)[17]), "=r"((r)[18]), "=r"((r)[19]), \
          "=r"((r)[20]), "=r"((r)[21]), "=r"((r)[22]), "=r"((r)[23]), \
          "=r"((r)[24]), "=r"((r)[25]), "=r"((r)[26]), "=r"((r)[27]), \
          "=r"((r)[28]), "=r"((r)[29]), "=r"((r)[30]), "=r"((r)[31]) \
        : "r"(addr))
#endif  // HAS_TCGEN05

// ---------------- fused prep: x -> fp16 (padded) + build W1^T ----------------
#define X2H_BLOCKS ((MPAD * IN_DIM / 4 + 255) / 256)
#define BW1_BLOCKS ((W1_COLS * IN_DIM + 255) / 256)
__global__ void k_prep1(const float* __restrict__ x, const float* __restrict__ bases,
                        const float* __restrict__ comp, const float* __restrict__ root) {
    if (blockIdx.x < X2H_BLOCKS) {
        int idx = blockIdx.x * 256 + threadIdx.x;
        if (idx >= MPAD * IN_DIM / 4) return;
        int row = idx / (IN_DIM / 4);
        __half2 h0 = __half2(__float2half(0.f), __float2half(0.f)), h1 = h0;
        if (row < N_NODES) {
            float4 v = *(const float4*)(x + (size_t)idx * 4);
            h0 = __floats2half2_rn(v.x, v.y);
            h1 = __floats2half2_rn(v.z, v.w);
        }
        __half2* o = (__half2*)g_xh + (size_t)idx * 2;
        o[0] = h0; o[1] = h1;
    } else {
        int idx = (blockIdx.x - X2H_BLOCKS) * 256 + threadIdx.x;
        if (idx >= W1_COLS * IN_DIM) return;
        int col = idx / IN_DIM, k = idx % IN_DIM;
        int r = col / HID_DIM, o = col % HID_DIM;
        float v;
        if (r == NREL) v = root[k * HID_DIM + o];
        else {
            v = 0.f;
#pragma unroll
            for (int b = 0; b < NB; b++)
                v += comp[r * NB + b] * bases[((size_t)b * IN_DIM + k) * HID_DIM + o];
        }
        g_W1t[idx] = __float2half(v);
    }
}

// ---------------- CSR build ----------------
__global__ void k_zero_counts() {
    int i = blockIdx.x * blockDim.x + threadIdx.x;
    if (i < N_NODES) g_counts[i] = 0;
}
__global__ void k_count(const int* __restrict__ ei) {
    int e = blockIdx.x * blockDim.x + threadIdx.x;
    if (e < N_EDGES) atomicAdd(&g_counts[ei[N_EDGES + e]], 1);
}
__global__ void __launch_bounds__(256) k_scan1() {
    int t = threadIdx.x, lane = t & 31, w = t >> 5;
    int i = blockIdx.x * 256 + t;
    int v = (i < N_NODES) ? g_counts[i] : 0;
    int x = v;
#pragma unroll
    for (int o = 1; o < 32; o <<= 1) {
        int y = __shfl_up_sync(0xffffffffu, x, o);
        if (lane >= o) x += y;
    }
    __shared__ int ws[8];
    if (lane == 31) ws[w] = x;
    __syncthreads();
    int add = 0;
#pragma unroll
    for (int k = 0; k < 8; k++) add += (k < w) ? ws[k] : 0;
    if (i < N_NODES) g_offsets[i] = x - v + add;
    if (t == 255) g_blocksum[blockIdx.x] = x + add;
}
__global__ void __launch_bounds__(128) k_scan2() {
    int t = threadIdx.x, lane = t & 31, w = t >> 5;
    int v = (t < SCAN_BLOCKS) ? g_blocksum[t] : 0;
    int x = v;
#pragma unroll
    for (int o = 1; o < 32; o <<= 1) {
        int y = __shfl_up_sync(0xffffffffu, x, o);
        if (lane >= o) x += y;
    }
    __shared__ int ws[4];
    if (lane == 31) ws[w] = x;
    __syncthreads();
    int add = 0;
#pragma unroll
    for (int k = 0; k < 4; k++) add += (k < w) ? ws[k] : 0;
    if (t < SCAN_BLOCKS) g_blocksum[t] = x - v + add;
}
__global__ void __launch_bounds__(256) k_scan3() {
    int i = blockIdx.x * 256 + threadIdx.x;
    if (i < N_NODES) {
        int o = g_offsets[i] + g_blocksum[blockIdx.x];
        g_offsets[i] = o;
        g_cursor[i]  = o;
    }
}
__global__ void k_scatter(const int* __restrict__ ei, const int* __restrict__ et) {
    int e = blockIdx.x * blockDim.x + threadIdx.x;
    if (e < N_EDGES) {
        int dst = ei[N_EDGES + e];
        int pos = atomicAdd(&g_cursor[dst], 1);
        g_rowid[pos] = ei[e] * (NREL + 1) + et[e];
    }
}

// ---------------- build W2^T (K-major, fp16) ----------------
__global__ void k_buildW2t(const float* __restrict__ bases, const float* __restrict__ comp,
                           const float* __restrict__ root) {
    int idx = blockIdx.x * blockDim.x + threadIdx.x;
    if (idx >= W2_COLS * HID_DIM) return;
    int col = idx / HID_DIM, k = idx % HID_DIM;
    int r = col / OUT_DIM, o = col % OUT_DIM;
    float v;
    if (r == NREL) v = root[k * OUT_DIM + o];
    else {
        v = 0.f;
#pragma unroll
        for (int b = 0; b < NB; b++)
            v += comp[r * NB + b] * bases[((size_t)b * HID_DIM + k) * OUT_DIM + o];
    }
    g_W2t[idx] = __float2half(v);
}

// ---------------- GEMM: C[rows,N](fp16) = A[rows,K](fp16) @ Bt[N,K]^T(fp16) ----------------
// 256 threads, CTA tile 128x128, K chunked by 128 (fp16 kind::f16 MMA, K=16/step).
__global__ void __launch_bounds__(256)
k_tc_gemm(const __half* __restrict__ A, const __half* __restrict__ Bt,
          __half* __restrict__ C, int Ktot, int N, int row0) {
#if HAS_TCGEN05
    extern __shared__ char smem[];
    const uint32_t sb = smem_u32(smem);
    char* sA = smem + 1024;
    char* sB = smem + 1024 + 32768;
    int tid = threadIdx.x, wid = tid >> 5, lid = tid & 31;
    int rowBase = (blockIdx.y + row0) * 128, colBase = blockIdx.x * 128;

    if (wid == 0) { tmem_alloc(sb, 128); tmem_relinquish(); }
    if (tid == 0) mbar_init(sb + 8, 1);
    __syncthreads();
    uint32_t tmem;
    asm volatile("ld.shared.b32 %0, [%1];" : "=r"(tmem) : "r"(sb));

    const uint32_t idesc = 0x8200010u;
    const uint64_t da = make_desc(sb + 1024);
    const uint64_t db = make_desc(sb + 1024 + 32768);

    int nKc = Ktot >> 7;                     // chunks of 128
    for (int kc = 0; kc < nKc; kc++) {
        if (kc > 0) mbar_wait(sb + 8, (kc - 1) & 1);
        int k0 = kc << 7;
#pragma unroll
        for (int i = 0; i < 8; i++) {
            int fid = i * 256 + tid;         // 2048 uint4 per tile
            int r = fid >> 4;                // 16 uint4 per 128-fp16 row
            int c = (fid & 15) * 8;
            uint4 va = *(const uint4*)(A + (size_t)(rowBase + r) * Ktot + k0 + c);
            sts_h8(sA, r, c, va);
            uint4 vb = *(const uint4*)(Bt + (size_t)(colBase + r) * Ktot + k0 + c);
            sts_h8(sB, r, c, vb);
        }
        asm volatile("fence.proxy.async.shared::cta;" ::: "memory");
        __syncthreads();
        if (wid == 0) {
            if (elect_one()) {
#pragma unroll
                for (int ks = 0; ks < 8; ks++) {   // K=16 per MMA
                    uint64_t off = (uint64_t)((ks >> 2) * 1024 + (ks & 3) * 2);
                    mma_f16_ss(tmem, da + off, db + off, idesc, (kc | ks) != 0);
                }
                tc_commit(sb + 8);
            }
        }
    }
    mbar_wait(sb + 8, (nKc - 1) & 1);
    asm volatile("tcgen05.fence::after_thread_sync;" ::: "memory");

    // epilogue: 8 warps; warp w -> rows (w&3)*32, col half (w>>2)*64; half2-packed staging
    uint32_t* hstg = (uint32_t*)(smem + 1024) + wid * (32 * 33);
    int rowOff = (wid & 3) * 32;
    int colOff = (wid >> 2) * 64;
    uint32_t rg0[32], rg1[32];
    LDTM_X32(rg0, tmem + colOff);
    LDTM_X32(rg1, tmem + colOff + 32);
    asm volatile("tcgen05.wait::ld.sync.aligned;" ::: "memory");
#pragma unroll
    for (int j = 0; j < 16; j++) {
        hstg[lid * 33 + j]      = pack_h2(rg0[2 * j], rg0[2 * j + 1]);
        hstg[lid * 33 + 16 + j] = pack_h2(rg1[2 * j], rg1[2 * j + 1]);
    }
    __syncwarp();
    uint32_t* crow = (uint32_t*)(C + (size_t)(rowBase + rowOff) * N + colBase + colOff);
#pragma unroll 4
    for (int rr = 0; rr < 32; rr++)
        crow[(size_t)rr * (N / 2) + lid] = hstg[rr * 33 + lid];

    asm volatile("tcgen05.fence::before_thread_sync;" ::: "memory");
    __syncthreads();
    if (wid == 0) tmem_dealloc(tmem, 128);
#else
    // ---- SIMT fallback (non-sm_103a passes), correctness only ----
    extern __shared__ char smem[];
    float* As = (float*)smem;
    float* Bs = (float*)smem + 8 * 128;
    int tid = threadIdx.x;
    int rowBase = (blockIdx.y + row0) * 128, colBase = blockIdx.x * 128;
    int tr = (tid >> 4) * 8;
    int tc = (tid & 15) * 8;

    float acc[8][8] = {};
    for (int k0 = 0; k0 < Ktot; k0 += 8) {
        if (tid < 128) {
            uint4 av = *(const uint4*)(A + (size_t)(rowBase + tid) * Ktot + k0);
            const __half2* ah = (const __half2*)&av;
#pragma unroll
            for (int j = 0; j < 4; j++) {
                float2 f = __half22float2(ah[j]);
                As[(2 * j) * 128 + tid] = f.x;
                As[(2 * j + 1) * 128 + tid] = f.y;
            }
        } else {
            int t2 = tid - 128;
            uint4 bv = *(const uint4*)(Bt + (size_t)(colBase + t2) * Ktot + k0);
            const __half2* bh = (const __half2*)&bv;
#pragma unroll
            for (int j = 0; j < 4; j++) {
                float2 f = __half22float2(bh[j]);
                Bs[(2 * j) * 128 + t2] = f.x;
                Bs[(2 * j + 1) * 128 + t2] = f.y;
            }
        }
        __syncthreads();
#pragma unroll
        for (int kk = 0; kk < 8; kk++) {
            float rm[8], rn[8];
#pragma unroll
            for (int i = 0; i < 8; i++) rm[i] = As[kk * 128 + tr + i];
#pragma unroll
            for (int j = 0; j < 8; j++) rn[j] = Bs[kk * 128 + tc + j];
#pragma unroll
            for (int i = 0; i < 8; i++)
#pragma unroll
                for (int j = 0; j < 8; j++) acc[i][j] += rm[i] * rn[j];
        }
        __syncthreads();
    }
#pragma unroll
    for (int i = 0; i < 8; i++) {
        int row = rowBase + tr + i;
#pragma unroll
        for (int j = 0; j < 8; j++)
            C[(size_t)row * N + colBase + tc + j] = __float2half(acc[i][j]);
    }
#endif
}

// ---------------- layer 1: gather-max + root + bias + LN + ReLU -> fp16 h ----------------
__global__ void __launch_bounds__(128) k_agg1(const float* __restrict__ bias,
                                              const float* __restrict__ gamma,
                                              const float* __restrict__ beta,
                                              int n0) {
    int n = blockIdx.x + n0;
    int t = threadIdx.x;
    if (n >= N_NODES) {
        ((__half2*)g_h)[(size_t)n * (HID_DIM / 2) + t] = __half2(__half(0.f), __half(0.f));
        return;
    }
    int start = g_offsets[n];
    int deg = g_counts[n];
    const __half2* Y = (const __half2*)g_Y1;

    float mx = -INFINITY, my = -INFINITY;
    int i = 0;
    for (; i + 4 <= deg; i += 4) {
        int r0 = g_rowid[start + i + 0];
        int r1 = g_rowid[start + i + 1];
        int r2 = g_rowid[start + i + 2];
        int r3 = g_rowid[start + i + 3];
        float2 f0 = __half22float2(Y[(size_t)r0 * (HID_DIM / 2) + t]);
        float2 f1 = __half22float2(Y[(size_t)r1 * (HID_DIM / 2) + t]);
        float2 f2 = __half22float2(Y[(size_t)r2 * (HID_DIM / 2) + t]);
        float2 f3 = __half22float2(Y[(size_t)r3 * (HID_DIM / 2) + t]);
        mx = fmaxf(fmaxf(fmaxf(mx, f0.x), fmaxf(f1.x, f2.x)), f3.x);
        my = fmaxf(fmaxf(fmaxf(my, f0.y), fmaxf(f1.y, f2.y)), f3.y);
    }
    for (; i < deg; i++) {
        int row = g_rowid[start + i];
        float2 f = __half22float2(Y[(size_t)row * (HID_DIM / 2) + t]);
        mx = fmaxf(mx, f.x);
        my = fmaxf(my, f.y);
    }
    if (deg == 0) { mx = 0.f; my = 0.f; }

    float2 rootv = __half22float2(Y[((size_t)n * W1_COLS + NREL * HID_DIM) / 2 + t]);
    float2 bi = ((const float2*)bias)[t];
    float vx = mx + rootv.x + bi.x;
    float vy = my + rootv.y + bi.y;

    float s = vx + vy, s2 = vx * vx + vy * vy;
#pragma unroll
    for (int o = 16; o > 0; o >>= 1) {
        s  += __shfl_xor_sync(0xffffffffu, s, o);
        s2 += __shfl_xor_sync(0xffffffffu, s2, o);
    }
    __shared__ float ws[4], ws2[4];
    int w = t >> 5, l = t & 31;
    if (l == 0) { ws[w] = s; ws2[w] = s2; }
    __syncthreads();
    float ts = ws[0] + ws[1] + ws[2] + ws[3];
    float ts2 = ws2[0] + ws2[1] + ws2[2] + ws2[3];
    float mean = ts * (1.f / HID_DIM);
    float var  = ts2 * (1.f / HID_DIM) - mean * mean;
    float rstd = rsqrtf(var + LN_EPS);
    float2 ga = ((const float2*)gamma)[t];
    float2 be = ((const float2*)beta)[t];
    float yx = (vx - mean) * rstd * ga.x + be.x;
    float yy = (vy - mean) * rstd * ga.y + be.y;
    ((__half2*)g_h)[(size_t)n * (HID_DIM / 2) + t] =
        __floats2half2_rn(fmaxf(yx, 0.f), fmaxf(yy, 0.f));
}

// ---------------- layer 2: gather-sum + root + bias + LN + log_softmax ----------------
__global__ void __launch_bounds__(256) k_agg2(const float* __restrict__ bias,
                                              const float* __restrict__ gamma,
                                              const float* __restrict__ beta,
                                              float* __restrict__ out) {
    int n = blockIdx.x * 8 + (threadIdx.x >> 5);
    if (n >= N_NODES) return;
    int lane = threadIdx.x & 31;
    int start = g_offsets[n];
    int deg = g_counts[n];
    const __half2* Y = (const __half2*)g_Y2;

    float sx = 0.f, sy = 0.f;
    int i = 0;
    for (; i + 4 <= deg; i += 4) {
        int r0 = g_rowid[start + i + 0];
        int r1 = g_rowid[start + i + 1];
        int r2 = g_rowid[start + i + 2];
        int r3 = g_rowid[start + i + 3];
        float2 f0 = __half22float2(Y[(size_t)r0 * (OUT_DIM / 2) + lane]);
        float2 f1 = __half22float2(Y[(size_t)r1 * (OUT_DIM / 2) + lane]);
        float2 f2 = __half22float2(Y[(size_t)r2 * (OUT_DIM / 2) + lane]);
        float2 f3 = __half22float2(Y[(size_t)r3 * (OUT_DIM / 2) + lane]);
        sx += (f0.x + f1.x) + (f2.x + f3.x);
        sy += (f0.y + f1.y) + (f2.y + f3.y);
    }
    for (; i < deg; i++) {
        int row = g_rowid[start + i];
        float2 f = __half22float2(Y[(size_t)row * (OUT_DIM / 2) + lane]);
        sx += f.x; sy += f.y;
    }
    float2 rootv = __half22float2(Y[((size_t)n * W2_COLS + NREL * OUT_DIM) / 2 + lane]);
    float2 bi = ((const float2*)bias)[lane];
    float vx = sx + rootv.x + bi.x;
    float vy = sy + rootv.y + bi.y;

    float a = vx + vy, b = vx * vx + vy * vy;
#pragma unroll
    for (int o = 16; o > 0; o >>= 1) {
        a += __shfl_xor_sync(0xffffffffu, a, o);
        b += __shfl_xor_sync(0xffffffffu, b, o);
    }
    float mean = a * (1.f / OUT_DIM);
    float var  = b * (1.f / OUT_DIM) - mean * mean;
    float rstd = rsqrtf(var + LN_EPS);
    float2 ga = ((const float2*)gamma)[lane];
    float2 be = ((const float2*)beta)[lane];
    float yx = (vx - mean) * rstd * ga.x + be.x;
    float yy = (vy - mean) * rstd * ga.y + be.y;

    float mx = fmaxf(yx, yy);
#pragma unroll
    for (int o = 16; o > 0; o >>= 1) mx = fmaxf(mx, __shfl_xor_sync(0xffffffffu, mx, o));
    float es = expf(yx - mx) + expf(yy - mx);
#pragma unroll
    for (int o = 16; o > 0; o >>= 1) es += __shfl_xor_sync(0xffffffffu, es, o);
    float lse = mx + logf(es);

    ((float2*)out)[(size_t)n * (OUT_DIM / 2) + lane] = make_float2(yx - lse, yy - lse);
}

// ---------------- host launch ----------------
extern "C" void kernel_launch(void* const* d_in, const int* in_sizes, int n_in,
                              void* d_out, int out_size) {
    const float* x      = (const float*)d_in[0];
    const int*   ei     = (const int*)d_in[1];
    const int*   et     = (const int*)d_in[2];
    const float* bases1 = (const float*)d_in[3];
    const float* comp1  = (const float*)d_in[4];
    const float* root1  = (const float*)d_in[5];
    const float* bias1  = (const float*)d_in[6];
    const float* g1     = (const float*)d_in[7];
    const float* b1     = (const float*)d_in[8];
    const float* bases2 = (const float*)d_in[9];
    const float* comp2  = (const float*)d_in[10];
    const float* root2  = (const float*)d_in[11];
    const float* bias2  = (const float*)d_in[12];
    const float* g2     = (const float*)d_in[13];
    const float* b2     = (const float*)d_in[14];
    float* out = (float*)d_out;

    __half *pxh, *pW1t, *pW2t, *pY1, *pY2, *ph;
    cudaGetSymbolAddress((void**)&pxh,  g_xh);
    cudaGetSymbolAddress((void**)&pW1t, g_W1t);
    cudaGetSymbolAddress((void**)&pW2t, g_W2t);
    cudaGetSymbolAddress((void**)&pY1,  g_Y1);
    cudaGetSymbolAddress((void**)&pY2,  g_Y2);
    cudaGetSymbolAddress((void**)&ph,   g_h);

    const int SMEM_GEMM = 1024 + 2 * 32768;   // 66560 B
    cudaFuncSetAttribute(k_tc_gemm, cudaFuncAttributeMaxDynamicSharedMemorySize, SMEM_GEMM);

    // lazy one-time stream/event creation (identical work every call)
    static cudaStream_t s2 = nullptr;
    static cudaEvent_t evFork = nullptr, evJoin = nullptr, evA = nullptr, evG2a = nullptr;
    if (s2 == nullptr) {
        cudaStreamCreateWithFlags(&s2, cudaStreamNonBlocking);
        cudaEventCreateWithFlags(&evFork, cudaEventDisableTiming);
        cudaEventCreateWithFlags(&evJoin, cudaEventDisableTiming);
        cudaEventCreateWithFlags(&evA, cudaEventDisableTiming);
        cudaEventCreateWithFlags(&evG2a, cudaEventDisableTiming);
    }

    // fork: CSR chain on s2
    cudaEventRecord(evFork, 0);
    cudaStreamWaitEvent(s2, evFork, 0);

    // --- side stream: CSR build + W2 ---
    k_zero_counts<<<(N_NODES + 255) / 256, 256, 0, s2>>>();
    k_count<<<(N_EDGES + 255) / 256, 256, 0, s2>>>(ei);
    k_scan1<<<SCAN_BLOCKS, 256, 0, s2>>>();
    k_scan2<<<1, 128, 0, s2>>>();
    k_scan3<<<SCAN_BLOCKS, 256, 0, s2>>>();
    k_scatter<<<(N_EDGES + 255) / 256, 256, 0, s2>>>(ei, et);
    k_buildW2t<<<(W2_COLS * HID_DIM + 255) / 256, 256, 0, s2>>>(bases2, comp2, root2);
    cudaEventRecord(evJoin, s2);

    // --- main stream: fused prep (x->fp16 + W1), GEMM1 ---
    k_prep1<<<X2H_BLOCKS + BW1_BLOCKS, 256>>>(x, bases1, comp1, root1);
    {
        dim3 grid(W1_COLS / 128, MPAD / 128);
        k_tc_gemm<<<grid, 256, SMEM_GEMM>>>(pxh, pW1t, pY1, IN_DIM, W1_COLS, 0);
    }

    // join: agg1 needs CSR + Y1 (+ W2 for the GEMM2a launched below)
    cudaStreamWaitEvent(0, evJoin, 0);

    // agg1 chunk 0, then chunk 1 in parallel with GEMM2 chunk 0 on s2
    k_agg1<<<MCHUNK0 * 128, 128>>>(bias1, g1, b1, 0);
    cudaEventRecord(evA, 0);
    cudaStreamWaitEvent(s2, evA, 0);
    {
        dim3 grid(W2_COLS / 128, MCHUNK0);
        k_tc_gemm<<<grid, 256, SMEM_GEMM, s2>>>(ph, pW2t, pY2, HID_DIM, W2_COLS, 0);
    }
    cudaEventRecord(evG2a, s2);

    k_agg1<<<MCHUNK1 * 128, 128>>>(bias1, g1, b1, MCHUNK0 * 128);
    {
        dim3 grid(W2_COLS / 128, MCHUNK1);
        k_tc_gemm<<<grid, 256, SMEM_GEMM>>>(ph, pW2t, pY2, HID_DIM, W2_COLS, MCHUNK0);
    }

    // agg2 needs both GEMM2 halves
    cudaStreamWaitEvent(0, evG2a, 0);
    k_agg2<<<(N_NODES + 7) / 8, 256>>>(bias2, g2, b2, out);
}